// round 5
// baseline (speedup 1.0000x reference)
#include <cuda_runtime.h>
#include <math.h>

// Problem constants
#define N_ROWS 32768
#define DIM    256
#define KCODES 1024
#define M_OUT  (N_ROWS * DIM)

// Tiling
#define BN 64            // rows per block
#define BK 128           // codes per k-chunk
#define BD 16            // d-slice per B-tile load
#define AS_STRIDE 68     // padded row stride (floats); 68*4B = 272B -> 16B-aligned rows

typedef unsigned long long u64;

// Scratch in device globals (no allocations allowed)
__device__ __align__(16) float g_cbT[KCODES * DIM];   // codebook transposed: [k][d]
__device__ __align__(16) float g_cnorm[KCODES];       // |c_k|^2
__device__ int    g_counts[KCODES];
__device__ double g_sqsum;

// packed dual-fp32 FMA: acc.{lo,hi} += a.{lo,hi} * b.{lo,hi}
__device__ __forceinline__ void ffma2(u64& acc, u64 a, u64 b) {
    asm("fma.rn.f32x2 %0, %1, %2, %0;" : "+l"(acc) : "l"(a), "l"(b));
}

// ---------------------------------------------------------------------------
// Prep: block per code k (1024 blocks). Transpose codebook, compute |c|^2,
// zero accumulators. Re-runs every launch -> graph-replay safe.
// ---------------------------------------------------------------------------
__global__ void vq_prep(const float* __restrict__ cb) {
    __shared__ float red[8];
    const int k = blockIdx.x;     // 0..1023
    const int d = threadIdx.x;    // 0..255
    float v = cb[(size_t)d * KCODES + k];
    g_cbT[k * DIM + d] = v;       // coalesced write
    float s = v * v;
    #pragma unroll
    for (int off = 16; off; off >>= 1) s += __shfl_xor_sync(0xffffffffu, s, off);
    if ((d & 31) == 0) red[d >> 5] = s;
    __syncthreads();
    if (d == 0) {
        float t = 0.0f;
        #pragma unroll
        for (int i = 0; i < 8; i++) t += red[i];
        g_cnorm[k] = t;
        g_counts[k] = 0;
        if (k == 0) g_sqsum = 0.0;
    }
}

// ---------------------------------------------------------------------------
// Main: fused distance-GEMM (packed f32x2 FMA) + argmin + gather + ste + MSE +
// histogram. One block per 64 rows. Warp ty owns rows ty*8..ty*8+7 (as 4
// row-pairs); lane tx owns codes tx*4..tx*4+3 of each 128-code chunk.
// ---------------------------------------------------------------------------
__global__ __launch_bounds__(256, 2)
void vq_main(const float* __restrict__ x, const float* __restrict__ cb,
             float* __restrict__ out) {
    extern __shared__ float smem[];
    float* As  = smem;                              // [DIM][AS_STRIDE], As[d][row]
    float* Bs2 = As + DIM * AS_STRIDE;              // [BD][2*BK] code values DUPLICATED in pairs
    int*   s_idx = (int*)(Bs2 + BD * 2 * BK);       // [BN]
    float* s_red = (float*)(s_idx + BN);            // [8]

    const int tid = threadIdx.x;
    const int tx  = tid & 31;
    const int ty  = tid >> 5;
    const int rowbase = blockIdx.x * BN;

    // ---- Load A tile (64 x 256) transposed into SMEM ----
    {
        const float4* xg = (const float4*)(x + (size_t)rowbase * DIM);
        #pragma unroll
        for (int i = 0; i < 16; i++) {
            int f  = tid + i * 256;
            int r  = f >> 6;
            int c4 = f & 63;
            float4 v = xg[f];
            int d = c4 * 4;
            As[(d + 0) * AS_STRIDE + r] = v.x;
            As[(d + 1) * AS_STRIDE + r] = v.y;
            As[(d + 2) * AS_STRIDE + r] = v.z;
            As[(d + 3) * AS_STRIDE + r] = v.w;
        }
    }
    __syncthreads();

    float bval[8];
    int   bidx[8];
    #pragma unroll
    for (int i = 0; i < 8; i++) { bval[i] = 3.4e38f; bidx[i] = 0; }

    // ---- k-chunk loop ----
    for (int k0 = 0; k0 < KCODES; k0 += BK) {
        u64 acc2[4][4];   // [row-pair][code]: lo = row 2i, hi = row 2i+1
        #pragma unroll
        for (int i = 0; i < 4; i++)
            #pragma unroll
            for (int j = 0; j < 4; j++) acc2[i][j] = 0ull;

        for (int d0 = 0; d0 < DIM; d0 += BD) {
            // load B tile with each code value duplicated into (b,b) pairs
            #pragma unroll
            for (int i = 0; i < 2; i++) {
                int f  = tid + i * 256;
                int dd = f >> 5;
                int c4 = f & 31;
                float4 v = *(const float4*)(cb + (size_t)(d0 + dd) * KCODES + k0 + c4 * 4);
                float* dst = &Bs2[dd * (2 * BK) + c4 * 8];
                *(float4*)(dst)     = make_float4(v.x, v.x, v.y, v.y);
                *(float4*)(dst + 4) = make_float4(v.z, v.z, v.w, v.w);
            }
            __syncthreads();

            #pragma unroll
            for (int dd = 0; dd < BD; dd++) {
                const float* ar = &As[(d0 + dd) * AS_STRIDE + (ty << 3)];
                ulonglong2 a01 = *(const ulonglong2*)(ar);      // row pairs (0,1),(2,3)
                ulonglong2 a23 = *(const ulonglong2*)(ar + 4);  // row pairs (4,5),(6,7)
                const float* br = &Bs2[dd * (2 * BK) + (tx << 3)];
                ulonglong2 b01 = *(const ulonglong2*)(br);      // dup pairs code j=0,1
                ulonglong2 b23 = *(const ulonglong2*)(br + 4);  // dup pairs code j=2,3
                u64 ap[4] = {a01.x, a01.y, a23.x, a23.y};
                u64 bp[4] = {b01.x, b01.y, b23.x, b23.y};
                #pragma unroll
                for (int i = 0; i < 4; i++)
                    #pragma unroll
                    for (int j = 0; j < 4; j++)
                        ffma2(acc2[i][j], ap[i], bp[j]);
            }
            __syncthreads();
        }

        // ---- argmin over this chunk (distance = |c|^2 - 2 x.c) ----
        float4 cn = *(const float4*)(&g_cnorm[k0 + (tx << 2)]);
        float cnv[4] = {cn.x, cn.y, cn.z, cn.w};
        #pragma unroll
        for (int i = 0; i < 4; i++) {
            #pragma unroll
            for (int h = 0; h < 2; h++) {
                const int r  = 2 * i + h;
                const int kk = k0 + (tx << 2);
                float bv = 3.4e38f; int bk = kk;
                #pragma unroll
                for (int j = 0; j < 4; j++) {
                    unsigned u = h ? (unsigned)(acc2[i][j] >> 32) : (unsigned)acc2[i][j];
                    float v = cnv[j] - 2.0f * __uint_as_float(u);
                    if (v < bv) { bv = v; bk = kk + j; }   // strict < keeps first index
                }
                #pragma unroll
                for (int off = 16; off; off >>= 1) {
                    float ov = __shfl_xor_sync(0xffffffffu, bv, off);
                    int   ok = __shfl_xor_sync(0xffffffffu, bk, off);
                    if (ov < bv || (ov == bv && ok < bk)) { bv = ov; bk = ok; }
                }
                if (bv < bval[r]) { bval[r] = bv; bidx[r] = bk; }
            }
        }
    }

    // ---- publish per-row best indices ----
    if (tx == 0) {
        #pragma unroll
        for (int i = 0; i < 8; i++) s_idx[(ty << 3) + i] = bidx[i];
    }
    __syncthreads();

    if (tid < BN) atomicAdd(&g_counts[s_idx[tid]], 1);

    // ---- epilogue: gather quantized rows, write ste, accumulate MSE ----
    float sq = 0.0f;
    const int d = tid;
    for (int r = 0; r < BN; r++) {
        int kb = s_idx[r];
        float q  = g_cbT[kb * DIM + d];
        float xv = As[d * AS_STRIDE + r];
        float df = q - xv;
        sq = fmaf(df, df, sq);
        out[(size_t)(rowbase + r) * DIM + d] = xv + df;
    }

    #pragma unroll
    for (int off = 16; off; off >>= 1) sq += __shfl_xor_sync(0xffffffffu, sq, off);
    if (tx == 0) s_red[ty] = sq;
    __syncthreads();
    if (tid == 0) {
        float t = 0.0f;
        #pragma unroll
        for (int i = 0; i < 8; i++) t += s_red[i];
        atomicAdd(&g_sqsum, (double)t);
    }
}

// ---------------------------------------------------------------------------
// Finalize: perplexity + losses
// ---------------------------------------------------------------------------
__global__ void vq_final(float* __restrict__ out) {
    __shared__ float red[32];
    int k = threadIdx.x;                 // 1024 threads
    float c = (float)g_counts[k];
    float p = c * (1.0f / (float)N_ROWS);
    float t = -p * logf(p + 1e-10f);
    #pragma unroll
    for (int off = 16; off; off >>= 1) t += __shfl_xor_sync(0xffffffffu, t, off);
    if ((k & 31) == 0) red[k >> 5] = t;
    __syncthreads();
    if (k < 32) {
        float v = red[k];
        #pragma unroll
        for (int off = 16; off; off >>= 1) v += __shfl_xor_sync(0xffffffffu, v, off);
        if (k == 0) {
            float perplexity = expf(v);
            float loss = (float)(g_sqsum / (double)M_OUT);
            out[M_OUT + 0] = perplexity;
            out[M_OUT + 1] = loss;           // codebook loss
            out[M_OUT + 2] = 0.25f * loss;   // commitment loss
        }
    }
}

// ---------------------------------------------------------------------------
// kernel_launch
// ---------------------------------------------------------------------------
extern "C" void kernel_launch(void* const* d_in, const int* in_sizes, int n_in,
                              void* d_out, int out_size) {
    const float* x  = (const float*)d_in[0];   // inputs (32,32,32,256) f32
    const float* cb = (const float*)d_in[1];   // codebook (256,1024) f32
    float* out = (float*)d_out;

    const int smem_bytes = DIM * AS_STRIDE * sizeof(float)     // As
                         + BD * 2 * BK * sizeof(float)         // Bs2 (duplicated)
                         + BN * sizeof(int)                    // s_idx
                         + 8 * sizeof(float);                  // s_red

    cudaFuncSetAttribute(vq_main, cudaFuncAttributeMaxDynamicSharedMemorySize, smem_bytes);

    vq_prep<<<KCODES, 256>>>(cb);
    vq_main<<<N_ROWS / BN, 256, smem_bytes>>>(x, cb, out);
    vq_final<<<1, KCODES>>>(out);
}

// round 9
// speedup vs baseline: 2.5297x; 2.5297x over previous
#include <cuda_runtime.h>
#include <cuda_bf16.h>
#include <math.h>

// ---------------- problem constants ----------------
#define N_ROWS 32768
#define DIM    256
#define KCODES 1024
#define M_OUT  (N_ROWS * DIM)

#define MT       128                // rows per CTA
#define NC       128                // codes per chunk
#define NCHUNKS  8
#define NSEG     12                 // 3 terms x 4 dim-slices of 64
#define NSEG_TOT (NCHUNKS * NSEG)   // 96

#define A_STRIDE 264                // bf16 elems; 528B rows -> conflict-free ldmatrix
#define B_STRIDE 72                 // bf16 elems; 144B rows
#define A_BYTES  (MT * A_STRIDE * 2)   // 67584
#define B_BYTES  (NC * B_STRIDE * 2)   // 18432

// smem byte offsets
#define SM_RED   0
#define SM_IDX   64                 // 128 ints
#define SM_CNORM 1024               // 1024 floats
#define SM_TOP   5120               // 128 rows x 2 wc x 16B = 4096
#define SM_A     9216               // A_hi
#define SM_AL    (SM_A + A_BYTES)   // A_lo
#define SM_B     (SM_AL + A_BYTES)  // 2 x B_BYTES
#define SMEM_TOTAL (SM_B + 2 * B_BYTES)   // 181248

typedef unsigned int u32;

// ---------------- device scratch (no allocations allowed) ----------------
__device__ __align__(16) __nv_bfloat16 g_a_hi[N_ROWS * DIM];
__device__ __align__(16) __nv_bfloat16 g_a_lo[N_ROWS * DIM];
__device__ __align__(16) __nv_bfloat16 g_b_hi[KCODES * DIM];   // [code][dim]
__device__ __align__(16) __nv_bfloat16 g_b_lo[KCODES * DIM];
__device__ __align__(16) float g_cbT[KCODES * DIM];            // exact fp32 [code][dim]
__device__ __align__(16) float g_cnorm[KCODES];
__device__ int    g_counts[KCODES];
__device__ double g_sqsum;

// ---------------- helpers ----------------
__device__ __forceinline__ u32 smem_u32(const void* p) {
    u32 a;
    asm("{ .reg .u64 t; cvta.to.shared.u64 t, %1; cvt.u32.u64 %0, t; }" : "=r"(a) : "l"(p));
    return a;
}
__device__ __forceinline__ void ldm_x4(u32* r, u32 addr) {
    asm volatile("ldmatrix.sync.aligned.m8n8.x4.shared.b16 {%0,%1,%2,%3}, [%4];"
                 : "=r"(r[0]), "=r"(r[1]), "=r"(r[2]), "=r"(r[3]) : "r"(addr));
}
__device__ __forceinline__ void mma16816(float* d, const u32* a, const u32* b) {
    asm volatile("mma.sync.aligned.m16n8k16.row.col.f32.bf16.bf16.f32 "
                 "{%0,%1,%2,%3}, {%4,%5,%6,%7}, {%8,%9}, {%0,%1,%2,%3};"
                 : "+f"(d[0]), "+f"(d[1]), "+f"(d[2]), "+f"(d[3])
                 : "r"(a[0]), "r"(a[1]), "r"(a[2]), "r"(a[3]), "r"(b[0]), "r"(b[1]));
}
#define CP_ASYNC16(sa, ga) \
    asm volatile("cp.async.cg.shared.global [%0], [%1], 16;" :: "r"(sa), "l"(ga))
#define CP_COMMIT() asm volatile("cp.async.commit_group;")

// ---------------- prep: split x into bf16 hi/lo ----------------
__global__ void vq_prep_x(const float* __restrict__ x) {
    int i = blockIdx.x * 256 + threadIdx.x;         // float4 index
    float4 v = ((const float4*)x)[i];
    __nv_bfloat16 h0 = __float2bfloat16_rn(v.x);
    __nv_bfloat16 h1 = __float2bfloat16_rn(v.y);
    __nv_bfloat16 h2 = __float2bfloat16_rn(v.z);
    __nv_bfloat16 h3 = __float2bfloat16_rn(v.w);
    __nv_bfloat16 l0 = __float2bfloat16_rn(v.x - __bfloat162float(h0));
    __nv_bfloat16 l1 = __float2bfloat16_rn(v.y - __bfloat162float(h1));
    __nv_bfloat16 l2 = __float2bfloat16_rn(v.z - __bfloat162float(h2));
    __nv_bfloat16 l3 = __float2bfloat16_rn(v.w - __bfloat162float(h3));
    __nv_bfloat162* ph = (__nv_bfloat162*)g_a_hi;
    __nv_bfloat162* pl = (__nv_bfloat162*)g_a_lo;
    ph[2*i]   = __halves2bfloat162(h0, h1);
    ph[2*i+1] = __halves2bfloat162(h2, h3);
    pl[2*i]   = __halves2bfloat162(l0, l1);
    pl[2*i+1] = __halves2bfloat162(l2, l3);
}

// ---------------- prep: codebook transpose, split, norms, zero accums ----------------
__global__ void vq_prep_cb(const float* __restrict__ cb) {
    __shared__ float red[8];
    const int k = blockIdx.x;     // code
    const int d = threadIdx.x;    // dim
    float v = cb[(size_t)d * KCODES + k];
    g_cbT[k * DIM + d] = v;
    __nv_bfloat16 h = __float2bfloat16_rn(v);
    g_b_hi[k * DIM + d] = h;
    g_b_lo[k * DIM + d] = __float2bfloat16_rn(v - __bfloat162float(h));
    float s = v * v;
    #pragma unroll
    for (int off = 16; off; off >>= 1) s += __shfl_xor_sync(0xffffffffu, s, off);
    if ((d & 31) == 0) red[d >> 5] = s;
    __syncthreads();
    if (d == 0) {
        float t = 0.0f;
        #pragma unroll
        for (int i = 0; i < 8; i++) t += red[i];
        g_cnorm[k] = t;
        g_counts[k] = 0;
        if (k == 0) g_sqsum = 0.0;
    }
}

// issue cp.async prefetch for global segment gs
__device__ __forceinline__ void prefetch_seg(int gs, int tid, u32 sb) {
    int chunk = gs / NSEG, t = gs % NSEG;
    const __nv_bfloat16* bsrc = (t < 8) ? ((t < 4) ? g_b_hi : g_b_lo) : g_b_hi;
    const __nv_bfloat16* gb = bsrc + (size_t)chunk * NC * DIM + (t & 3) * 64;
    u32 bbase = sb + SM_B + (gs & 1) * B_BYTES;
    #pragma unroll
    for (int i = 0; i < 4; i++) {
        int lin = i * 256 + tid;          // 1024 x 16B chunks
        int code = lin >> 3, j = lin & 7;
        u32 sa = bbase + (u32)(code * B_STRIDE + j * 8) * 2;
        CP_ASYNC16(sa, gb + (size_t)code * DIM + j * 8);
    }
    CP_COMMIT();
}

// ---------------- main: HMMA distance GEMM + top-2 + exact rescore ----------------
__global__ __launch_bounds__(256, 1)
void vq_main(const float* __restrict__ x, float* __restrict__ out) {
    extern __shared__ char smem[];
    const u32 sb = smem_u32(smem);
    const int tid  = threadIdx.x;
    const int lane = tid & 31, wid = tid >> 5;
    const int wr = wid >> 1, wc = wid & 1;        // warp row (M), warp col (N)
    const int tg = lane & 3, g = lane >> 2;       // quad id / group id
    const int rowbase = blockIdx.x * MT;

    // ---- load A hi/lo tiles into smem (padded rows) ----
    #pragma unroll
    for (int part = 0; part < 2; part++) {
        const __nv_bfloat16* src = part ? g_a_lo : g_a_hi;
        char* dst = smem + (part ? SM_AL : SM_A);
        #pragma unroll 4
        for (int it = 0; it < 16; it++) {
            int lin = it * 256 + tid;     // 4096 x 16B chunks
            int r = lin >> 5, j = lin & 31;
            uint4 v = *(const uint4*)(src + (size_t)(rowbase + r) * DIM + j * 8);
            *(uint4*)(dst + (r * A_STRIDE + j * 8) * 2) = v;
        }
    }
    for (int i = tid; i < KCODES; i += 256)
        *(float*)(smem + SM_CNORM + i * 4) = g_cnorm[i];

    // ldmatrix per-lane address components
    const int a_row = lane & 15;
    const int a_k8  = (lane >> 4) * 8;
    const int b_code = ((lane >> 4) & 1) * 8 + (lane & 7);
    const int b_k8   = ((lane >> 3) & 1) * 8;

    // running top-2 per row-slot (4 rows per thread)
    float t1v[4], t2v[4]; int t1k[4], t2k[4];
    #pragma unroll
    for (int s = 0; s < 4; s++) { t1v[s] = t2v[s] = 3.4e38f; t1k[s] = 0; t2k[s] = 1; }

    float acc[2][8][4];

    prefetch_seg(0, tid, sb);
    __syncthreads();   // A tiles + cnorm visible

    for (int gs = 0; gs < NSEG_TOT; gs++) {
        const int t = gs % NSEG;
        const int chunk = gs / NSEG;
        if (t == 0) {
            #pragma unroll
            for (int m = 0; m < 2; m++)
                #pragma unroll
                for (int n = 0; n < 8; n++)
                    #pragma unroll
                    for (int q = 0; q < 4; q++) acc[m][n][q] = 0.0f;
        }
        if (gs + 1 < NSEG_TOT) {
            prefetch_seg(gs + 1, tid, sb);
            asm volatile("cp.async.wait_group 1;");
        } else {
            asm volatile("cp.async.wait_group 0;");
        }
        __syncthreads();

        const u32 abase  = sb + ((t < 8) ? SM_A : SM_AL);
        const int dimoff = (t & 3) * 64;
        const u32 bbase  = sb + SM_B + (gs & 1) * B_BYTES;

        #pragma unroll
        for (int ks = 0; ks < 4; ks++) {
            const int acol = dimoff + ks * 16;
            u32 af[2][4];
            #pragma unroll
            for (int m = 0; m < 2; m++)
                ldm_x4(af[m], abase + (u32)((32 * wr + 16 * m + a_row) * A_STRIDE + acol + a_k8) * 2);
            u32 bf[8][2];
            #pragma unroll
            for (int p = 0; p < 4; p++) {
                u32 r[4];
                ldm_x4(r, bbase + (u32)((wc * 64 + p * 16 + b_code) * B_STRIDE + ks * 16 + b_k8) * 2);
                bf[2*p][0] = r[0]; bf[2*p][1] = r[1];
                bf[2*p+1][0] = r[2]; bf[2*p+1][1] = r[3];
            }
            #pragma unroll
            for (int m = 0; m < 2; m++)
                #pragma unroll
                for (int n = 0; n < 8; n++)
                    mma16816(acc[m][n], af[m], bf[n]);
        }

        if (t == NSEG - 1) {
            // epilogue: distances for this chunk -> running top-2
            #pragma unroll
            for (int m = 0; m < 2; m++)
                #pragma unroll
                for (int h = 0; h < 2; h++) {
                    const int s = 2 * m + h;
                    #pragma unroll
                    for (int n = 0; n < 8; n++) {
                        const int code0 = chunk * NC + wc * 64 + n * 8 + 2 * tg;
                        float cn0 = *(float*)(smem + SM_CNORM + code0 * 4);
                        float cn1 = *(float*)(smem + SM_CNORM + (code0 + 1) * 4);
                        float v0 = cn0 - 2.0f * acc[m][n][2 * h + 0];
                        float v1 = cn1 - 2.0f * acc[m][n][2 * h + 1];
                        if (v0 < t1v[s]) { t2v[s]=t1v[s]; t2k[s]=t1k[s]; t1v[s]=v0; t1k[s]=code0; }
                        else if (v0 < t2v[s]) { t2v[s]=v0; t2k[s]=code0; }
                        if (v1 < t1v[s]) { t2v[s]=t1v[s]; t2k[s]=t1k[s]; t1v[s]=v1; t1k[s]=code0+1; }
                        else if (v1 < t2v[s]) { t2v[s]=v1; t2k[s]=code0+1; }
                    }
                }
        }
        __syncthreads();   // guard B buffer reuse by next iteration's prefetch
    }

    // ---- quad reduce top-2 across lanes (same rows live in groups of 4 lanes) ----
    #pragma unroll
    for (int off = 1; off <= 2; off <<= 1) {
        #pragma unroll
        for (int s = 0; s < 4; s++) {
            float u1 = __shfl_xor_sync(0xffffffffu, t1v[s], off);
            int   j1 = __shfl_xor_sync(0xffffffffu, t1k[s], off);
            float u2 = __shfl_xor_sync(0xffffffffu, t2v[s], off);
            int   j2 = __shfl_xor_sync(0xffffffffu, t2k[s], off);
            if (u1 < t1v[s] || (u1 == t1v[s] && j1 < t1k[s])) {
                t2v[s]=t1v[s]; t2k[s]=t1k[s]; t1v[s]=u1; t1k[s]=j1;
            } else if (u1 < t2v[s] || (u1 == t2v[s] && j1 < t2k[s])) { t2v[s]=u1; t2k[s]=j1; }
            if (u2 < t1v[s] || (u2 == t1v[s] && j2 < t1k[s])) {
                t2v[s]=t1v[s]; t2k[s]=t1k[s]; t1v[s]=u2; t1k[s]=j2;
            } else if (u2 < t2v[s] || (u2 == t2v[s] && j2 < t2k[s])) { t2v[s]=u2; t2k[s]=j2; }
        }
    }
    if (tg == 0) {
        #pragma unroll
        for (int s = 0; s < 4; s++) {
            const int row = 32 * wr + 16 * (s >> 1) + 8 * (s & 1) + g;
            char* dst = smem + SM_TOP + (row * 2 + wc) * 16;
            *(float*)(dst + 0) = t1v[s];
            *(int*)  (dst + 4) = t1k[s];
            *(float*)(dst + 8) = t2v[s];
            *(int*)  (dst + 12) = t2k[s];
        }
    }
    __syncthreads();

    // ---- merge wc halves, exact fp32 rescore of top-2, pick final index ----
    if (tid < MT) {
        float m1v = 3.4e38f, m2v = 3.4e38f; int m1k = 0, m2k = 1;
        #pragma unroll
        for (int w = 0; w < 2; w++) {
            const char* src = smem + SM_TOP + (tid * 2 + w) * 16;
            #pragma unroll
            for (int e = 0; e < 2; e++) {
                float v = *(const float*)(src + e * 8);
                int   k = *(const int*)(src + e * 8 + 4);
                if (v < m1v || (v == m1v && k < m1k)) { m2v=m1v; m2k=m1k; m1v=v; m1k=k; }
                else if (v < m2v || (v == m2v && k < m2k)) { m2v=v; m2k=k; }
            }
        }
        const float* xr = x + (size_t)(rowbase + tid) * DIM;
        const float* c1 = g_cbT + (size_t)m1k * DIM;
        const float* c2 = g_cbT + (size_t)m2k * DIM;
        float d1 = 0.0f, d2 = 0.0f;
        #pragma unroll 8
        for (int d = 0; d < DIM; d += 4) {
            float4 xv = *(const float4*)(xr + d);
            float4 q1 = *(const float4*)(c1 + d);
            float4 q2 = *(const float4*)(c2 + d);
            d1 = fmaf(xv.x, q1.x, fmaf(xv.y, q1.y, fmaf(xv.z, q1.z, fmaf(xv.w, q1.w, d1))));
            d2 = fmaf(xv.x, q2.x, fmaf(xv.y, q2.y, fmaf(xv.z, q2.z, fmaf(xv.w, q2.w, d2))));
        }
        float s1 = g_cnorm[m1k] - 2.0f * d1;
        float s2 = g_cnorm[m2k] - 2.0f * d2;
        int kf = (s2 < s1 || (s2 == s1 && m2k < m1k)) ? m2k : m1k;
        *(int*)(smem + SM_IDX + tid * 4) = kf;
        atomicAdd(&g_counts[kf], 1);
    }
    __syncthreads();

    // ---- ste write + MSE (exact fp32, coalesced; thread owns one dim col) ----
    float sq = 0.0f;
    for (int r = 0; r < MT; r++) {
        int kb = *(int*)(smem + SM_IDX + r * 4);
        float q  = g_cbT[(size_t)kb * DIM + tid];
        float xv = x[(size_t)(rowbase + r) * DIM + tid];
        float df = q - xv;
        sq = fmaf(df, df, sq);
        out[(size_t)(rowbase + r) * DIM + tid] = xv + df;
    }
    #pragma unroll
    for (int off = 16; off; off >>= 1) sq += __shfl_xor_sync(0xffffffffu, sq, off);
    if ((tid & 31) == 0) *(float*)(smem + SM_RED + wid * 4) = sq;
    __syncthreads();
    if (tid == 0) {
        float tt = 0.0f;
        #pragma unroll
        for (int i = 0; i < 8; i++) tt += *(float*)(smem + SM_RED + i * 4);
        atomicAdd(&g_sqsum, (double)tt);
    }
}

// ---------------- finalize ----------------
__global__ void vq_final(float* __restrict__ out) {
    __shared__ float red[32];
    int k = threadIdx.x;                 // 1024 threads
    float c = (float)g_counts[k];
    float p = c * (1.0f / (float)N_ROWS);
    float t = -p * logf(p + 1e-10f);
    #pragma unroll
    for (int off = 16; off; off >>= 1) t += __shfl_xor_sync(0xffffffffu, t, off);
    if ((k & 31) == 0) red[k >> 5] = t;
    __syncthreads();
    if (k < 32) {
        float v = red[k];
        #pragma unroll
        for (int off = 16; off; off >>= 1) v += __shfl_xor_sync(0xffffffffu, v, off);
        if (k == 0) {
            out[M_OUT + 0] = expf(v);
            float loss = (float)(g_sqsum / (double)M_OUT);
            out[M_OUT + 1] = loss;           // codebook loss
            out[M_OUT + 2] = 0.25f * loss;   // commitment loss
        }
    }
}

// ---------------- launch ----------------
extern "C" void kernel_launch(void* const* d_in, const int* in_sizes, int n_in,
                              void* d_out, int out_size) {
    const float* x  = (const float*)d_in[0];   // (32,32,32,256) f32
    const float* cb = (const float*)d_in[1];   // (256,1024) f32
    float* out = (float*)d_out;

    cudaFuncSetAttribute(vq_main, cudaFuncAttributeMaxDynamicSharedMemorySize, SMEM_TOTAL);

    vq_prep_x<<<M_OUT / 4 / 256, 256>>>(x);
    vq_prep_cb<<<KCODES, 256>>>(cb);
    vq_main<<<N_ROWS / MT, 256, SMEM_TOTAL>>>(x, out);
    vq_final<<<1, KCODES>>>(out);
}

// round 17
// speedup vs baseline: 3.8831x; 1.5350x over previous
#include <cuda_runtime.h>
#include <cuda_bf16.h>
#include <math.h>

// ---------------- problem constants ----------------
#define N_ROWS 32768
#define DIM    256
#define KCODES 1024
#define M_OUT  (N_ROWS * DIM)

#define MT       128                // rows per CTA
#define NC       128                // codes per chunk
#define NCHUNKS  8
#define NSEG_TOT 16                 // 8 chunks x 2 dim-slices of 128

#define A_STRIDE 264                // bf16 elems; 528B rows -> conflict-free ldmatrix
#define B_STRIDE 136                // bf16 elems; 272B rows -> conflict-free ldmatrix
#define A_BYTES  (MT * A_STRIDE * 2)   // 67584
#define B_BYTES  (NC * B_STRIDE * 2)   // 34816

// smem byte offsets
#define SM_RED   0
#define SM_IDX   64                 // 128 ints
#define SM_CNORM 1024               // 1024 floats
#define SM_TOP   5120               // 128 rows x 2 wc x 4 entries x 8B = 8192
#define SM_A     13312
#define SM_B     (SM_A + A_BYTES)   // 2 x B_BYTES
#define SMEM_TOTAL (SM_B + 2 * B_BYTES)   // 150528

typedef unsigned int u32;

// ---------------- device scratch (no allocations allowed) ----------------
__device__ __align__(16) __nv_bfloat16 g_a_hi[N_ROWS * DIM];
__device__ __align__(16) __nv_bfloat16 g_b_hi[KCODES * DIM];   // [code][dim]
__device__ __align__(16) float g_cbT[KCODES * DIM];            // exact fp32 [code][dim]
__device__ __align__(16) float g_cnorm[KCODES];
__device__ int    g_counts[KCODES];
__device__ double g_sqsum;

// ---------------- helpers ----------------
__device__ __forceinline__ u32 smem_u32(const void* p) {
    u32 a;
    asm("{ .reg .u64 t; cvta.to.shared.u64 t, %1; cvt.u32.u64 %0, t; }" : "=r"(a) : "l"(p));
    return a;
}
__device__ __forceinline__ void ldm_x4(u32* r, u32 addr) {
    asm volatile("ldmatrix.sync.aligned.m8n8.x4.shared.b16 {%0,%1,%2,%3}, [%4];"
                 : "=r"(r[0]), "=r"(r[1]), "=r"(r[2]), "=r"(r[3]) : "r"(addr));
}
__device__ __forceinline__ void mma16816(float* d, const u32* a, const u32* b) {
    asm volatile("mma.sync.aligned.m16n8k16.row.col.f32.bf16.bf16.f32 "
                 "{%0,%1,%2,%3}, {%4,%5,%6,%7}, {%8,%9}, {%0,%1,%2,%3};"
                 : "+f"(d[0]), "+f"(d[1]), "+f"(d[2]), "+f"(d[3])
                 : "r"(a[0]), "r"(a[1]), "r"(a[2]), "r"(a[3]), "r"(b[0]), "r"(b[1]));
}
#define CP_ASYNC16(sa, ga) \
    asm volatile("cp.async.cg.shared.global [%0], [%1], 16;" :: "r"(sa), "l"(ga))
#define CP_COMMIT() asm volatile("cp.async.commit_group;")

// sorted-4 insert (ascending, tv[0] = best); approx values -> ties don't matter here
__device__ __forceinline__ void ins4(float v, int k, float* tv, int* tk) {
    if (v < tv[3]) {
        if (v < tv[1]) {
            if (v < tv[0]) {
                tv[3]=tv[2]; tk[3]=tk[2]; tv[2]=tv[1]; tk[2]=tk[1];
                tv[1]=tv[0]; tk[1]=tk[0]; tv[0]=v; tk[0]=k;
            } else {
                tv[3]=tv[2]; tk[3]=tk[2]; tv[2]=tv[1]; tk[2]=tk[1]; tv[1]=v; tk[1]=k;
            }
        } else {
            if (v < tv[2]) { tv[3]=tv[2]; tk[3]=tk[2]; tv[2]=v; tk[2]=k; }
            else           { tv[3]=v; tk[3]=k; }
        }
    }
}

// ---------------- prep: x -> bf16 (hi only) ----------------
__global__ void vq_prep_x(const float* __restrict__ x) {
    int i = blockIdx.x * 256 + threadIdx.x;         // float4 index
    float4 v = ((const float4*)x)[i];
    __nv_bfloat162* ph = (__nv_bfloat162*)g_a_hi;
    ph[2*i]   = __halves2bfloat162(__float2bfloat16_rn(v.x), __float2bfloat16_rn(v.y));
    ph[2*i+1] = __halves2bfloat162(__float2bfloat16_rn(v.z), __float2bfloat16_rn(v.w));
}

// ---------------- prep: codebook transpose, bf16, norms, zero accums ----------------
__global__ void vq_prep_cb(const float* __restrict__ cb) {
    __shared__ float red[8];
    const int k = blockIdx.x;     // code
    const int d = threadIdx.x;    // dim
    float v = cb[(size_t)d * KCODES + k];
    g_cbT[k * DIM + d] = v;
    g_b_hi[k * DIM + d] = __float2bfloat16_rn(v);
    float s = v * v;
    #pragma unroll
    for (int off = 16; off; off >>= 1) s += __shfl_xor_sync(0xffffffffu, s, off);
    if ((d & 31) == 0) red[d >> 5] = s;
    __syncthreads();
    if (d == 0) {
        float t = 0.0f;
        #pragma unroll
        for (int i = 0; i < 8; i++) t += red[i];
        g_cnorm[k] = t;
        g_counts[k] = 0;
        if (k == 0) g_sqsum = 0.0;
    }
}

// issue cp.async prefetch for global segment gs (chunk = gs/2, dim-half = gs&1)
__device__ __forceinline__ void prefetch_seg(int gs, int tid, u32 sb) {
    int chunk = gs >> 1, t = gs & 1;
    const __nv_bfloat16* gb = g_b_hi + (size_t)chunk * NC * DIM + t * 128;
    u32 bbase = sb + SM_B + (u32)(gs & 1) * B_BYTES;
    #pragma unroll
    for (int i = 0; i < 8; i++) {
        int lin = i * 256 + tid;          // 2048 x 16B chunks
        int code = lin >> 4, j = lin & 15;
        u32 sa = bbase + (u32)(code * B_STRIDE + j * 8) * 2;
        CP_ASYNC16(sa, gb + (size_t)code * DIM + j * 8);
    }
    CP_COMMIT();
}

// ---------------- main: 1-term HMMA distance GEMM + top-4 + exact rescore ----------------
__global__ __launch_bounds__(256, 1)
void vq_main(const float* __restrict__ x, float* __restrict__ out) {
    extern __shared__ char smem[];
    const u32 sb = smem_u32(smem);
    const int tid  = threadIdx.x;
    const int lane = tid & 31, wid = tid >> 5;
    const int wr = wid >> 1, wc = wid & 1;        // warp row (M), warp col (N)
    const int tg = lane & 3, g = lane >> 2;       // quad id / group id
    const int rowbase = blockIdx.x * MT;

    // ---- load A tile (padded rows) + cnorm ----
    #pragma unroll 4
    for (int it = 0; it < 16; it++) {
        int lin = it * 256 + tid;     // 4096 x 16B chunks
        int r = lin >> 5, j = lin & 31;
        uint4 v = *(const uint4*)(g_a_hi + (size_t)(rowbase + r) * DIM + j * 8);
        *(uint4*)(smem + SM_A + (r * A_STRIDE + j * 8) * 2) = v;
    }
    for (int i = tid; i < KCODES; i += 256)
        *(float*)(smem + SM_CNORM + i * 4) = g_cnorm[i];

    // ldmatrix per-lane address components
    const int a_row = lane & 15;
    const int a_k8  = (lane >> 4) * 8;
    const int b_code = ((lane >> 4) & 1) * 8 + (lane & 7);
    const int b_k8   = ((lane >> 3) & 1) * 8;

    // running top-4 per row-slot (4 rows per thread)
    float tv[4][4]; int tk[4][4];
    #pragma unroll
    for (int s = 0; s < 4; s++)
        #pragma unroll
        for (int e = 0; e < 4; e++) { tv[s][e] = 3.4e38f; tk[s][e] = e; }

    float acc[2][8][4];

    prefetch_seg(0, tid, sb);
    __syncthreads();   // A tile + cnorm visible

    for (int gs = 0; gs < NSEG_TOT; gs++) {
        const int t = gs & 1;
        const int chunk = gs >> 1;
        if (t == 0) {
            #pragma unroll
            for (int m = 0; m < 2; m++)
                #pragma unroll
                for (int n = 0; n < 8; n++)
                    #pragma unroll
                    for (int q = 0; q < 4; q++) acc[m][n][q] = 0.0f;
        }
        if (gs + 1 < NSEG_TOT) {
            prefetch_seg(gs + 1, tid, sb);
            asm volatile("cp.async.wait_group 1;");
        } else {
            asm volatile("cp.async.wait_group 0;");
        }
        __syncthreads();

        const int dimoff = t * 128;
        const u32 bbase  = sb + SM_B + (u32)(gs & 1) * B_BYTES;

        #pragma unroll
        for (int ks = 0; ks < 8; ks++) {
            const int acol = dimoff + ks * 16;
            u32 af[2][4];
            #pragma unroll
            for (int m = 0; m < 2; m++)
                ldm_x4(af[m], sb + SM_A + (u32)((32 * wr + 16 * m + a_row) * A_STRIDE + acol + a_k8) * 2);
            u32 bf[8][2];
            #pragma unroll
            for (int p = 0; p < 4; p++) {
                u32 r[4];
                ldm_x4(r, bbase + (u32)((wc * 64 + p * 16 + b_code) * B_STRIDE + ks * 16 + b_k8) * 2);
                bf[2*p][0] = r[0]; bf[2*p][1] = r[1];
                bf[2*p+1][0] = r[2]; bf[2*p+1][1] = r[3];
            }
            #pragma unroll
            for (int m = 0; m < 2; m++)
                #pragma unroll
                for (int n = 0; n < 8; n++)
                    mma16816(acc[m][n], af[m], bf[n]);
        }

        if (t == 1) {
            // epilogue: approx distances for this chunk -> running top-4
            #pragma unroll
            for (int m = 0; m < 2; m++)
                #pragma unroll
                for (int h = 0; h < 2; h++) {
                    const int s = 2 * m + h;
                    #pragma unroll
                    for (int n = 0; n < 8; n++) {
                        const int code0 = chunk * NC + wc * 64 + n * 8 + 2 * tg;
                        float cn0 = *(float*)(smem + SM_CNORM + code0 * 4);
                        float cn1 = *(float*)(smem + SM_CNORM + (code0 + 1) * 4);
                        ins4(cn0 - 2.0f * acc[m][n][2 * h + 0], code0,     tv[s], tk[s]);
                        ins4(cn1 - 2.0f * acc[m][n][2 * h + 1], code0 + 1, tv[s], tk[s]);
                    }
                }
        }
        __syncthreads();   // guard B buffer reuse by next iteration's prefetch
    }

    // ---- quad butterfly merge of top-4 (snapshot remote before inserting) ----
    #pragma unroll
    for (int off = 1; off <= 2; off <<= 1) {
        #pragma unroll
        for (int s = 0; s < 4; s++) {
            float rv[4]; int rk[4];
            #pragma unroll
            for (int e = 0; e < 4; e++) {
                rv[e] = __shfl_xor_sync(0xffffffffu, tv[s][e], off);
                rk[e] = __shfl_xor_sync(0xffffffffu, tk[s][e], off);
            }
            #pragma unroll
            for (int e = 0; e < 4; e++) ins4(rv[e], rk[e], tv[s], tk[s]);
        }
    }
    if (tg == 0) {
        #pragma unroll
        for (int s = 0; s < 4; s++) {
            const int row = 32 * wr + 16 * (s >> 1) + 8 * (s & 1) + g;
            char* dst = smem + SM_TOP + (row * 2 + wc) * 32;
            #pragma unroll
            for (int e = 0; e < 4; e++) {
                *(float*)(dst + e * 8)     = tv[s][e];
                *(int*)  (dst + e * 8 + 4) = tk[s][e];
            }
        }
    }
    __syncthreads();

    // ---- merge wc halves -> top-4 candidates, exact fp32 rescore, pick final ----
    if (tid < MT) {
        float mv[4]; int mk[4];
        #pragma unroll
        for (int e = 0; e < 4; e++) { mv[e] = 3.4e38f; mk[e] = e; }
        #pragma unroll
        for (int w = 0; w < 2; w++) {
            const char* src = smem + SM_TOP + (tid * 2 + w) * 32;
            #pragma unroll
            for (int e = 0; e < 4; e++)
                ins4(*(const float*)(src + e * 8), *(const int*)(src + e * 8 + 4), mv, mk);
        }
        const float* xr = x + (size_t)(rowbase + tid) * DIM;
        const float* c0 = g_cbT + (size_t)mk[0] * DIM;
        const float* c1 = g_cbT + (size_t)mk[1] * DIM;
        const float* c2 = g_cbT + (size_t)mk[2] * DIM;
        const float* c3 = g_cbT + (size_t)mk[3] * DIM;
        float d0 = 0.0f, d1 = 0.0f, d2 = 0.0f, d3 = 0.0f;
        #pragma unroll 4
        for (int d = 0; d < DIM; d += 4) {
            float4 xv = *(const float4*)(xr + d);
            float4 q0 = *(const float4*)(c0 + d);
            float4 q1 = *(const float4*)(c1 + d);
            float4 q2 = *(const float4*)(c2 + d);
            float4 q3 = *(const float4*)(c3 + d);
            d0 = fmaf(xv.x, q0.x, fmaf(xv.y, q0.y, fmaf(xv.z, q0.z, fmaf(xv.w, q0.w, d0))));
            d1 = fmaf(xv.x, q1.x, fmaf(xv.y, q1.y, fmaf(xv.z, q1.z, fmaf(xv.w, q1.w, d1))));
            d2 = fmaf(xv.x, q2.x, fmaf(xv.y, q2.y, fmaf(xv.z, q2.z, fmaf(xv.w, q2.w, d2))));
            d3 = fmaf(xv.x, q3.x, fmaf(xv.y, q3.y, fmaf(xv.z, q3.z, fmaf(xv.w, q3.w, d3))));
        }
        float se[4];
        se[0] = g_cnorm[mk[0]] - 2.0f * d0;
        se[1] = g_cnorm[mk[1]] - 2.0f * d1;
        se[2] = g_cnorm[mk[2]] - 2.0f * d2;
        se[3] = g_cnorm[mk[3]] - 2.0f * d3;
        float bv = se[0]; int bk = mk[0];
        #pragma unroll
        for (int e = 1; e < 4; e++)
            if (se[e] < bv || (se[e] == bv && mk[e] < bk)) { bv = se[e]; bk = mk[e]; }
        *(int*)(smem + SM_IDX + tid * 4) = bk;
        atomicAdd(&g_counts[bk], 1);
    }
    __syncthreads();

    // ---- ste write + MSE (exact fp32, coalesced; thread owns one dim col) ----
    float sq = 0.0f;
    for (int r = 0; r < MT; r++) {
        int kb = *(int*)(smem + SM_IDX + r * 4);
        float q  = g_cbT[(size_t)kb * DIM + tid];
        float xv = x[(size_t)(rowbase + r) * DIM + tid];
        float df = q - xv;
        sq = fmaf(df, df, sq);
        out[(size_t)(rowbase + r) * DIM + tid] = xv + df;
    }
    #pragma unroll
    for (int off = 16; off; off >>= 1) sq += __shfl_xor_sync(0xffffffffu, sq, off);
    if ((tid & 31) == 0) *(float*)(smem + SM_RED + wid * 4) = sq;
    __syncthreads();
    if (tid == 0) {
        float tt = 0.0f;
        #pragma unroll
        for (int i = 0; i < 8; i++) tt += *(float*)(smem + SM_RED + i * 4);
        atomicAdd(&g_sqsum, (double)tt);
    }
}

// ---------------- finalize ----------------
__global__ void vq_final(float* __restrict__ out) {
    __shared__ float red[32];
    int k = threadIdx.x;                 // 1024 threads
    float c = (float)g_counts[k];
    float p = c * (1.0f / (float)N_ROWS);
    float t = -p * logf(p + 1e-10f);
    #pragma unroll
    for (int off = 16; off; off >>= 1) t += __shfl_xor_sync(0xffffffffu, t, off);
    if ((k & 31) == 0) red[k >> 5] = t;
    __syncthreads();
    if (k < 32) {
        float v = red[k];
        #pragma unroll
        for (int off = 16; off; off >>= 1) v += __shfl_xor_sync(0xffffffffu, v, off);
        if (k == 0) {
            out[M_OUT + 0] = expf(v);
            float loss = (float)(g_sqsum / (double)M_OUT);
            out[M_OUT + 1] = loss;           // codebook loss
            out[M_OUT + 2] = 0.25f * loss;   // commitment loss
        }
    }
}

// ---------------- launch ----------------
extern "C" void kernel_launch(void* const* d_in, const int* in_sizes, int n_in,
                              void* d_out, int out_size) {
    const float* x  = (const float*)d_in[0];   // (32,32,32,256) f32
    const float* cb = (const float*)d_in[1];   // (256,1024) f32
    float* out = (float*)d_out;

    cudaFuncSetAttribute(vq_main, cudaFuncAttributeMaxDynamicSharedMemorySize, SMEM_TOTAL);

    vq_prep_x<<<M_OUT / 4 / 256, 256>>>(x);
    vq_prep_cb<<<KCODES, 256>>>(cb);
    vq_main<<<N_ROWS / MT, 256, SMEM_TOTAL>>>(x, out);
    vq_final<<<1, KCODES>>>(out);
}